// round 1
// baseline (speedup 1.0000x reference)
#include <cuda_runtime.h>

#define NN 400      // nodes
#define FD 240      // node feature dim
#define CD 32       // stack channels
#define LD 1440     // labels
#define NIN 304     // F + 2C

// ---------------- scratch (device globals; no allocation allowed) ----------------
__device__ float g_U[NN * CD];        // x @ sw[0:F]   + sb
__device__ float g_V[NN * CD];        // x @ sw[F:2F]
__device__ float g_aggi[NN * CD];
__device__ float g_aggj[NN * CD];
__device__ float g_e1[NN * NN];       // layer-1 e_out
__device__ float g_x1[NN * FD];       // layer-1 x_out
__device__ float g_x2[NN * FD];       // layer-2 x_out

// ---------------- proj: U[i][c] = sb[c] + sum_f x[i][f] sw[f][c]; V likewise ----
// grid = NN, block = 64 (threads 0..31 -> U, 32..63 -> V)
template <bool LAYER2>
__global__ void proj_kernel(const float* __restrict__ x_in,
                            const float* __restrict__ sw,
                            const float* __restrict__ sb)
{
    __shared__ float xs[FD];
    const float* xp = LAYER2 ? g_x1 : x_in;
    int i = blockIdx.x;
    for (int f = threadIdx.x; f < FD; f += blockDim.x) xs[f] = xp[i * FD + f];
    __syncthreads();
    int t = threadIdx.x;
    int c = t & 31;
    const float* w = sw + ((t < 32) ? 0 : FD * CD);
    float acc = (t < 32) ? sb[c] : 0.f;
#pragma unroll 8
    for (int f = 0; f < FD; f++) acc = fmaf(xs[f], w[f * CD + c], acc);
    if (t < 32) g_U[i * CD + c] = acc;
    else        g_V[i * CD + c] = acc;
}

// ---------------- pairwise combine + gates + aggregation ----------------
// One block per node i. Block owns BOTH row i (for agg_i) and column i (for agg_j).
// lane = channel c. 8 warps stride over the partner index m. No atomics.
template <bool WRITE_E, bool USE_E1>
__global__ void __launch_bounds__(256, 4)
pair_kernel(const float* __restrict__ a,
            const float* __restrict__ e_in,
            const float* __restrict__ sw,
            const float* __restrict__ aiw, const float* __restrict__ aib,
            const float* __restrict__ ajw, const float* __restrict__ ajb,
            const float* __restrict__ ew,  const float* __restrict__ eb)
{
    const float* e = USE_E1 ? g_e1 : e_in;
    int i    = blockIdx.x;
    int lane = threadIdx.x & 31;
    int warp = threadIdx.x >> 5;   // 0..7
    int c    = lane;

    float cv = sw[480 * CD + c];   // weight row for e
    float dv = sw[481 * CD + c];   // weight row for e^T
    float wi = aiw[c], wj = ajw[c];
    float we = WRITE_E ? ew[c] : 0.f;
    float bi = aib[0], bj = ajb[0];
    float be = WRITE_E ? eb[0] : 0.f;

    float Ui = g_U[i * CD + c];
    float Vi = g_V[i * CD + c];

    float acc_i = 0.f, acc_j = 0.f;

    for (int m = warp; m < NN; m += 8) {
        float Um  = g_U[m * CD + c];
        float Vm  = g_V[m * CD + c];
        float eim = e[i * NN + m];
        float emi = e[m * NN + i];
        float aim = a[i * NN + m];
        float ami = a[m * NN + i];

        // s(i,m): pair (target=i, source=m);  s(m,i): pair (target=m, source=i)
        float srow = fmaxf(fmaf(eim, cv, fmaf(emi, dv, Ui + Vm)), 0.f) * aim;
        float scol = fmaxf(fmaf(emi, cv, fmaf(eim, dv, Um + Vi)), 0.f) * ami;

        float d1 = srow * wi;                 // att_i logit for pair (i,m)
        float d2 = scol * wj;                 // att_j logit for pair (m,i)
        float d3 = WRITE_E ? srow * we : 0.f; // e_out for pair (i,m)
#pragma unroll
        for (int o = 16; o > 0; o >>= 1) {
            d1 += __shfl_xor_sync(0xffffffffu, d1, o);
            d2 += __shfl_xor_sync(0xffffffffu, d2, o);
            if (WRITE_E) d3 += __shfl_xor_sync(0xffffffffu, d3, o);
        }
        float atti = 1.f / (1.f + __expf(-(d1 + bi)));
        float attj = 1.f / (1.f + __expf(-(d2 + bj)));
        acc_i = fmaf(atti, srow, acc_i);
        acc_j = fmaf(attj, scol, acc_j);
        if (WRITE_E && lane == 0) g_e1[i * NN + m] = d3 + be;
    }

    __shared__ float si[8][CD], sj[8][CD];
    si[warp][c] = acc_i;
    sj[warp][c] = acc_j;
    __syncthreads();
    if (threadIdx.x < CD) {
        float ti = 0.f, tj = 0.f;
#pragma unroll
        for (int w = 0; w < 8; w++) { ti += si[w][threadIdx.x]; tj += sj[w][threadIdx.x]; }
        g_aggi[i * CD + threadIdx.x] = ti;
        g_aggj[i * CD + threadIdx.x] = tj;
    }
}

// ---------------- node model: x_out = [x, agg_i, agg_j] @ nw + nb --------------
// grid = 25 (16 nodes each), block = 240 (one output feature per thread),
// 16 accumulators per thread so nw is read once per 16 rows.
#define TIN 16
template <int LAYER>
__global__ void node_kernel(const float* __restrict__ x_in,
                            const float* __restrict__ nw,
                            const float* __restrict__ nb)
{
    __shared__ float s_in[TIN][NIN];
    const float* xp = (LAYER == 1) ? x_in : g_x1;
    float* xo       = (LAYER == 1) ? g_x1 : g_x2;
    int i0 = blockIdx.x * TIN;

    for (int idx = threadIdx.x; idx < TIN * NIN; idx += blockDim.x) {
        int r = idx / NIN, k = idx % NIN;
        int node = i0 + r;
        float v;
        if (k < FD)            v = xp[node * FD + k];
        else if (k < FD + CD)  v = g_aggi[node * CD + (k - FD)];
        else                   v = g_aggj[node * CD + (k - FD - CD)];
        s_in[r][k] = v;
    }
    __syncthreads();

    int o = threadIdx.x;  // 0..239
    float acc[TIN];
    float b = nb[o];
#pragma unroll
    for (int r = 0; r < TIN; r++) acc[r] = b;
    for (int k = 0; k < NIN; k++) {
        float w = nw[k * FD + o];
#pragma unroll
        for (int r = 0; r < TIN; r++) acc[r] = fmaf(s_in[r][k], w, acc[r]);
    }
#pragma unroll
    for (int r = 0; r < TIN; r++) xo[(i0 + r) * FD + o] = acc[r];
}

// ---------------- final dense: out = x2 @ dw + db ------------------------------
// grid = (5, 25), block = 288. 16 rows per thread.
#define TID 16
__global__ void dense_kernel(const float* __restrict__ dw,
                             const float* __restrict__ db,
                             float* __restrict__ out)
{
    __shared__ float xs[TID][FD];
    int i0 = blockIdx.y * TID;
    int o  = blockIdx.x * blockDim.x + threadIdx.x;  // 0..1439

    for (int idx = threadIdx.x; idx < TID * FD; idx += blockDim.x) {
        int r = idx / FD, f = idx % FD;
        xs[r][f] = g_x2[(i0 + r) * FD + f];
    }
    __syncthreads();

    float acc[TID];
    float b = db[o];
#pragma unroll
    for (int r = 0; r < TID; r++) acc[r] = b;
    for (int f = 0; f < FD; f++) {
        float w = dw[f * LD + o];
#pragma unroll
        for (int r = 0; r < TID; r++) acc[r] = fmaf(xs[r][f], w, acc[r]);
    }
#pragma unroll
    for (int r = 0; r < TID; r++) out[(i0 + r) * LD + o] = acc[r];
}

// ---------------- launch --------------------------------------------------------
extern "C" void kernel_launch(void* const* d_in, const int* in_sizes, int n_in,
                              void* d_out, int out_size)
{
    const float* x  = (const float*)d_in[0];
    const float* a  = (const float*)d_in[1];
    const float* e  = (const float*)d_in[2];
    const float* c1_sw  = (const float*)d_in[3];
    const float* c1_sb  = (const float*)d_in[4];
    const float* c1_aiw = (const float*)d_in[5];
    const float* c1_aib = (const float*)d_in[6];
    const float* c1_ajw = (const float*)d_in[7];
    const float* c1_ajb = (const float*)d_in[8];
    const float* c1_nw  = (const float*)d_in[9];
    const float* c1_nb  = (const float*)d_in[10];
    const float* c1_ew  = (const float*)d_in[11];
    const float* c1_eb  = (const float*)d_in[12];
    const float* c2_sw  = (const float*)d_in[13];
    const float* c2_sb  = (const float*)d_in[14];
    const float* c2_aiw = (const float*)d_in[15];
    const float* c2_aib = (const float*)d_in[16];
    const float* c2_ajw = (const float*)d_in[17];
    const float* c2_ajb = (const float*)d_in[18];
    const float* c2_nw  = (const float*)d_in[19];
    const float* c2_nb  = (const float*)d_in[20];
    const float* c2_ew  = (const float*)d_in[21];
    const float* c2_eb  = (const float*)d_in[22];
    const float* dw = (const float*)d_in[23];
    const float* db = (const float*)d_in[24];
    float* out = (float*)d_out;

    // ---- layer 1 ----
    proj_kernel<false><<<NN, 64>>>(x, c1_sw, c1_sb);
    pair_kernel<true, false><<<NN, 256>>>(a, e, c1_sw,
                                          c1_aiw, c1_aib, c1_ajw, c1_ajb,
                                          c1_ew, c1_eb);
    node_kernel<1><<<NN / TIN, FD>>>(x, c1_nw, c1_nb);

    // ---- layer 2 (e_out of layer 2 is dead: final output uses x only) ----
    proj_kernel<true><<<NN, 64>>>(x, c2_sw, c2_sb);
    pair_kernel<false, true><<<NN, 256>>>(a, e, c2_sw,
                                          c2_aiw, c2_aib, c2_ajw, c2_ajb,
                                          c2_ew, c2_eb);
    node_kernel<2><<<NN / TIN, FD>>>(x, c2_nw, c2_nb);

    // ---- final dense ----
    dense_kernel<<<dim3(LD / 288, NN / TID), 288>>>(dw, db, out);
}

// round 2
// speedup vs baseline: 1.2800x; 1.2800x over previous
#include <cuda_runtime.h>

#define NN 400      // nodes
#define FD 240      // node feature dim
#define CD 32       // stack channels
#define LD 1440     // labels
#define NIN 304     // F + 2C

// ---------------- scratch (device globals; no allocation allowed) ----------------
__device__ float g_U[NN * CD];        // x @ sw[0:F]   + sb
__device__ float g_V[NN * CD];        // x @ sw[F:2F]
__device__ float g_attI[NN * NN];     // sigmoid att_i gate per pair (p,q)
__device__ float g_attJ[NN * NN];     // sigmoid att_j gate per pair (p,q)
__device__ float g_aggi[NN * CD];
__device__ float g_aggj[NN * CD];
__device__ float g_e1[NN * NN];       // layer-1 e_out
__device__ float g_x1[NN * FD];       // layer-1 x_out
__device__ float g_x2[NN * FD];       // layer-2 x_out

// ---------------- proj: U[i][c] = sb[c] + sum_f x[i][f] sw[f][c]; V likewise ----
// grid = NN, block = 256. 4-way k-split over f, shared reduce.
template <bool LAYER2>
__global__ void __launch_bounds__(256)
proj_kernel(const float* __restrict__ x_in,
            const float* __restrict__ sw,
            const float* __restrict__ sb)
{
    __shared__ float xs[FD];
    __shared__ float red[4][64];
    const float* xp = LAYER2 ? g_x1 : x_in;
    int i = blockIdx.x;
    for (int f = threadIdx.x; f < FD; f += 256) xs[f] = xp[i * FD + f];
    __syncthreads();

    int ks  = threadIdx.x >> 6;   // 0..3  (k-split slice of 60)
    int c64 = threadIdx.x & 63;   // 0..31 -> U channel, 32..63 -> V channel
    int c   = c64 & 31;
    const float* w = sw + ((c64 < 32) ? 0 : FD * CD) + c;
    float acc = 0.f;
    int f0 = ks * 60;
#pragma unroll 15
    for (int f = f0; f < f0 + 60; f++) acc = fmaf(xs[f], w[f * CD], acc);
    red[ks][c64] = acc;
    __syncthreads();
    if (threadIdx.x < 64) {
        int t = threadIdx.x;
        float s = red[0][t] + red[1][t] + red[2][t] + red[3][t];
        if (t < 32) g_U[i * CD + t] = s + sb[t];
        else        g_V[i * CD + c] = s;
    }
}

// ---------------- att: per-pair gates (no cross-lane reduction) -----------------
// grid = NN (p), block = 416, thread = partner q. One stack eval per pair gives
// att_i logit, att_j logit, and (layer 1) e_out via serial 32-channel dots.
template <bool WRITE_E, bool USE_E1>
__global__ void __launch_bounds__(416)
att_kernel(const float* __restrict__ a, const float* __restrict__ e_in,
           const float* __restrict__ sw,
           const float* __restrict__ aiw, const float* __restrict__ aib,
           const float* __restrict__ ajw, const float* __restrict__ ajb,
           const float* __restrict__ ew,  const float* __restrict__ eb)
{
    const float* e = USE_E1 ? g_e1 : e_in;
    __shared__ float su[CD], scv[CD], sdv[CD], swi[CD], swj[CD], swe[CD];
    int p = blockIdx.x;
    if (threadIdx.x < CD) {
        int c = threadIdx.x;
        su[c]  = g_U[p * CD + c];
        scv[c] = sw[480 * CD + c];
        sdv[c] = sw[481 * CD + c];
        swi[c] = aiw[c];
        swj[c] = ajw[c];
        swe[c] = WRITE_E ? ew[c] : 0.f;
    }
    __syncthreads();
    int q = threadIdx.x;
    if (q >= NN) return;

    float epq = e[p * NN + q];
    float eqp = e[q * NN + p];
    float apq = a[p * NN + q];
    const float4* vq = (const float4*)(g_V + q * CD);
    float d1 = 0.f, d2 = 0.f, d3 = 0.f;
#pragma unroll
    for (int cc = 0; cc < 8; cc++) {
        float4 v = vq[cc];
        float vv[4] = {v.x, v.y, v.z, v.w};
#pragma unroll
        for (int k = 0; k < 4; k++) {
            int c = cc * 4 + k;
            float s = fmaxf(fmaf(epq, scv[c], fmaf(eqp, sdv[c], su[c] + vv[k])), 0.f) * apq;
            d1 = fmaf(s, swi[c], d1);
            d2 = fmaf(s, swj[c], d2);
            if (WRITE_E) d3 = fmaf(s, swe[c], d3);
        }
    }
    g_attI[p * NN + q] = 1.f / (1.f + __expf(-(d1 + aib[0])));
    g_attJ[p * NN + q] = 1.f / (1.f + __expf(-(d2 + ajb[0])));
    if (WRITE_E) g_e1[p * NN + q] = d3 + eb[0];
}

// ---------------- agg: recompute stack, scale by precomputed gates --------------
// Block per node n (owns row n for agg_i AND column n for agg_j). lane = channel,
// 8 warps stride partners m. No shuffles, no atomics.
template <bool USE_E1>
__global__ void __launch_bounds__(256)
agg_kernel(const float* __restrict__ a, const float* __restrict__ e_in,
           const float* __restrict__ sw)
{
    const float* e = USE_E1 ? g_e1 : e_in;
    int n    = blockIdx.x;
    int lane = threadIdx.x & 31;
    int warp = threadIdx.x >> 5;
    int c    = lane;

    float cv = sw[480 * CD + c];
    float dv = sw[481 * CD + c];
    float Un = g_U[n * CD + c];
    float Vn = g_V[n * CD + c];

    float acc_i = 0.f, acc_j = 0.f;
    for (int m = warp; m < NN; m += 8) {
        float Um  = g_U[m * CD + c];
        float Vm  = g_V[m * CD + c];
        float enm = e[n * NN + m];
        float emn = e[m * NN + n];
        float anm = a[n * NN + m];
        float amn = a[m * NN + n];
        float atI = g_attI[n * NN + m];
        float atJ = g_attJ[m * NN + n];

        float srow = fmaxf(fmaf(enm, cv, fmaf(emn, dv, Un + Vm)), 0.f) * anm;
        float scol = fmaxf(fmaf(emn, cv, fmaf(enm, dv, Um + Vn)), 0.f) * amn;
        acc_i = fmaf(atI, srow, acc_i);
        acc_j = fmaf(atJ, scol, acc_j);
    }

    __shared__ float si[8][CD], sj[8][CD];
    si[warp][c] = acc_i;
    sj[warp][c] = acc_j;
    __syncthreads();
    if (threadIdx.x < CD) {
        float ti = 0.f, tj = 0.f;
#pragma unroll
        for (int w = 0; w < 8; w++) { ti += si[w][threadIdx.x]; tj += sj[w][threadIdx.x]; }
        g_aggi[n * CD + threadIdx.x] = ti;
        g_aggj[n * CD + threadIdx.x] = tj;
    }
}

// ---------------- node model: x_out = [x, agg_i, agg_j] @ nw + nb --------------
#define TIN 8
template <int LAYER>
__global__ void node_kernel(const float* __restrict__ x_in,
                            const float* __restrict__ nw,
                            const float* __restrict__ nb)
{
    __shared__ float s_in[TIN][NIN];
    const float* xp = (LAYER == 1) ? x_in : g_x1;
    float* xo       = (LAYER == 1) ? g_x1 : g_x2;
    int i0 = blockIdx.x * TIN;

    for (int idx = threadIdx.x; idx < TIN * NIN; idx += blockDim.x) {
        int r = idx / NIN, k = idx % NIN;
        int node = i0 + r;
        float v;
        if (k < FD)            v = xp[node * FD + k];
        else if (k < FD + CD)  v = g_aggi[node * CD + (k - FD)];
        else                   v = g_aggj[node * CD + (k - FD - CD)];
        s_in[r][k] = v;
    }
    __syncthreads();

    int o = threadIdx.x;  // 0..239
    float acc[TIN];
    float b = nb[o];
#pragma unroll
    for (int r = 0; r < TIN; r++) acc[r] = b;
    for (int k = 0; k < NIN; k++) {
        float w = nw[k * FD + o];
#pragma unroll
        for (int r = 0; r < TIN; r++) acc[r] = fmaf(s_in[r][k], w, acc[r]);
    }
#pragma unroll
    for (int r = 0; r < TIN; r++) xo[(i0 + r) * FD + o] = acc[r];
}

// ---------------- final dense: out = x2 @ dw + db ------------------------------
#define TID 16
__global__ void dense_kernel(const float* __restrict__ dw,
                             const float* __restrict__ db,
                             float* __restrict__ out)
{
    __shared__ float xs[TID][FD];
    int i0 = blockIdx.y * TID;
    int o  = blockIdx.x * blockDim.x + threadIdx.x;  // 0..1439

    for (int idx = threadIdx.x; idx < TID * FD; idx += blockDim.x) {
        int r = idx / FD, f = idx % FD;
        xs[r][f] = g_x2[(i0 + r) * FD + f];
    }
    __syncthreads();

    float acc[TID];
    float b = db[o];
#pragma unroll
    for (int r = 0; r < TID; r++) acc[r] = b;
    for (int f = 0; f < FD; f++) {
        float w = dw[f * LD + o];
#pragma unroll
        for (int r = 0; r < TID; r++) acc[r] = fmaf(xs[r][f], w, acc[r]);
    }
#pragma unroll
    for (int r = 0; r < TID; r++) out[(i0 + r) * LD + o] = acc[r];
}

// ---------------- launch --------------------------------------------------------
extern "C" void kernel_launch(void* const* d_in, const int* in_sizes, int n_in,
                              void* d_out, int out_size)
{
    const float* x  = (const float*)d_in[0];
    const float* a  = (const float*)d_in[1];
    const float* e  = (const float*)d_in[2];
    const float* c1_sw  = (const float*)d_in[3];
    const float* c1_sb  = (const float*)d_in[4];
    const float* c1_aiw = (const float*)d_in[5];
    const float* c1_aib = (const float*)d_in[6];
    const float* c1_ajw = (const float*)d_in[7];
    const float* c1_ajb = (const float*)d_in[8];
    const float* c1_nw  = (const float*)d_in[9];
    const float* c1_nb  = (const float*)d_in[10];
    const float* c1_ew  = (const float*)d_in[11];
    const float* c1_eb  = (const float*)d_in[12];
    const float* c2_sw  = (const float*)d_in[13];
    const float* c2_sb  = (const float*)d_in[14];
    const float* c2_aiw = (const float*)d_in[15];
    const float* c2_aib = (const float*)d_in[16];
    const float* c2_ajw = (const float*)d_in[17];
    const float* c2_ajb = (const float*)d_in[18];
    const float* c2_nw  = (const float*)d_in[19];
    const float* c2_nb  = (const float*)d_in[20];
    const float* c2_ew  = (const float*)d_in[21];
    const float* c2_eb  = (const float*)d_in[22];
    const float* dw = (const float*)d_in[23];
    const float* db = (const float*)d_in[24];
    float* out = (float*)d_out;

    // ---- layer 1 ----
    proj_kernel<false><<<NN, 256>>>(x, c1_sw, c1_sb);
    att_kernel<true, false><<<NN, 416>>>(a, e, c1_sw,
                                         c1_aiw, c1_aib, c1_ajw, c1_ajb,
                                         c1_ew, c1_eb);
    agg_kernel<false><<<NN, 256>>>(a, e, c1_sw);
    node_kernel<1><<<NN / TIN, FD>>>(x, c1_nw, c1_nb);

    // ---- layer 2 (layer-2 e_out is dead: final output uses x only) ----
    proj_kernel<true><<<NN, 256>>>(x, c2_sw, c2_sb);
    att_kernel<false, true><<<NN, 416>>>(a, e, c2_sw,
                                         c2_aiw, c2_aib, c2_ajw, c2_ajb,
                                         c2_ew, c2_eb);
    agg_kernel<true><<<NN, 256>>>(a, e, c2_sw);
    node_kernel<2><<<NN / TIN, FD>>>(x, c2_nw, c2_nb);

    // ---- final dense ----
    dense_kernel<<<dim3(LD / 288, NN / TID), 288>>>(dw, db, out);
}

// round 3
// speedup vs baseline: 1.6272x; 1.2712x over previous
#include <cuda_runtime.h>

#define NN 400      // nodes
#define FD 240      // node feature dim
#define CD 32       // stack channels
#define LD 1440     // labels
#define NIN 304     // F + 2C

// ---------------- scratch (device globals; no allocation allowed) ----------------
__device__ float g_U[NN * CD];        // x @ sw[0:F]   + sb
__device__ float g_V[NN * CD];        // x @ sw[F:2F]
__device__ float g_attI[NN * NN];     // sigmoid att_i gate per pair (p,q)
__device__ float g_attJ[NN * NN];     // sigmoid att_j gate per pair (p,q)
__device__ float g_aggi[NN * CD];
__device__ float g_aggj[NN * CD];
__device__ float g_e1[NN * NN];       // layer-1 e_out
__device__ float g_x1[NN * FD];       // layer-1 x_out
__device__ float g_x2[NN * FD];       // layer-2 x_out

// ---------------- proj: U[i][c] = sb[c] + sum_f x[i][f] sw[f][c]; V likewise ----
// grid = NN, block = 256. 4-way k-split over f, shared reduce.
template <bool LAYER2>
__global__ void __launch_bounds__(256)
proj_kernel(const float* __restrict__ x_in,
            const float* __restrict__ sw,
            const float* __restrict__ sb)
{
    __shared__ float xs[FD];
    __shared__ float red[4][64];
    const float* xp = LAYER2 ? g_x1 : x_in;
    int i = blockIdx.x;
    for (int f = threadIdx.x; f < FD; f += 256) xs[f] = xp[i * FD + f];
    __syncthreads();

    int ks  = threadIdx.x >> 6;   // 0..3  (k-split slice of 60)
    int c64 = threadIdx.x & 63;   // 0..31 -> U channel, 32..63 -> V channel
    int c   = c64 & 31;
    const float* w = sw + ((c64 < 32) ? 0 : FD * CD) + c;
    float acc = 0.f;
    int f0 = ks * 60;
#pragma unroll 15
    for (int f = f0; f < f0 + 60; f++) acc = fmaf(xs[f], w[f * CD], acc);
    red[ks][c64] = acc;
    __syncthreads();
    if (threadIdx.x < 64) {
        int t = threadIdx.x;
        float s = red[0][t] + red[1][t] + red[2][t] + red[3][t];
        if (t < 32) g_U[i * CD + t] = s + sb[t];
        else        g_V[i * CD + c] = s;
    }
}

// ---------------- att: per-pair gates (no cross-lane reduction) -----------------
// grid = NN (p), block = 416, thread = partner q. One stack eval per pair gives
// att_i logit, att_j logit, and (layer 1) e_out via serial 32-channel dots.
// Per-channel tables staged in shared as float4.
template <bool WRITE_E, bool USE_E1>
__global__ void __launch_bounds__(416)
att_kernel(const float* __restrict__ a, const float* __restrict__ e_in,
           const float* __restrict__ sw,
           const float* __restrict__ aiw, const float* __restrict__ aib,
           const float* __restrict__ ajw, const float* __restrict__ ajb,
           const float* __restrict__ ew,  const float* __restrict__ eb)
{
    const float* e = USE_E1 ? g_e1 : e_in;
    __shared__ float4 su[8], scv[8], sdv[8], swi[8], swj[8], swe[8];
    int p = blockIdx.x;
    if (threadIdx.x < 8) {
        int t = threadIdx.x;
        su[t]  = ((const float4*)(g_U + p * CD))[t];
        scv[t] = ((const float4*)(sw + 480 * CD))[t];
        sdv[t] = ((const float4*)(sw + 481 * CD))[t];
        swi[t] = ((const float4*)aiw)[t];
        swj[t] = ((const float4*)ajw)[t];
        swe[t] = WRITE_E ? ((const float4*)ew)[t] : make_float4(0.f, 0.f, 0.f, 0.f);
    }
    __syncthreads();
    int q = threadIdx.x;
    if (q >= NN) return;

    float epq = e[p * NN + q];
    float eqp = e[q * NN + p];
    float apq = a[p * NN + q];
    const float4* vq = (const float4*)(g_V + q * CD);
    float d1 = 0.f, d2 = 0.f, d3 = 0.f;
#pragma unroll
    for (int cc = 0; cc < 8; cc++) {
        float4 v  = vq[cc];
        float4 u  = su[cc],  c4 = scv[cc], dd = sdv[cc];
        float4 wi = swi[cc], wj = swj[cc], we = swe[cc];
        float s;
        s = fmaxf(fmaf(epq, c4.x, fmaf(eqp, dd.x, u.x + v.x)), 0.f) * apq;
        d1 = fmaf(s, wi.x, d1); d2 = fmaf(s, wj.x, d2); if (WRITE_E) d3 = fmaf(s, we.x, d3);
        s = fmaxf(fmaf(epq, c4.y, fmaf(eqp, dd.y, u.y + v.y)), 0.f) * apq;
        d1 = fmaf(s, wi.y, d1); d2 = fmaf(s, wj.y, d2); if (WRITE_E) d3 = fmaf(s, we.y, d3);
        s = fmaxf(fmaf(epq, c4.z, fmaf(eqp, dd.z, u.z + v.z)), 0.f) * apq;
        d1 = fmaf(s, wi.z, d1); d2 = fmaf(s, wj.z, d2); if (WRITE_E) d3 = fmaf(s, we.z, d3);
        s = fmaxf(fmaf(epq, c4.w, fmaf(eqp, dd.w, u.w + v.w)), 0.f) * apq;
        d1 = fmaf(s, wi.w, d1); d2 = fmaf(s, wj.w, d2); if (WRITE_E) d3 = fmaf(s, we.w, d3);
    }
    g_attI[p * NN + q] = 1.f / (1.f + __expf(-(d1 + aib[0])));
    g_attJ[p * NN + q] = 1.f / (1.f + __expf(-(d2 + ajb[0])));
    if (WRITE_E) g_e1[p * NN + q] = d3 + eb[0];
}

// ---------------- agg: recompute stack, scale by precomputed gates --------------
// Block per node n (owns row n for agg_i AND column n for agg_j). lane = channel,
// 8 warps stride partners m. No shuffles, no atomics.
template <bool USE_E1>
__global__ void __launch_bounds__(256)
agg_kernel(const float* __restrict__ a, const float* __restrict__ e_in,
           const float* __restrict__ sw)
{
    const float* e = USE_E1 ? g_e1 : e_in;
    int n    = blockIdx.x;
    int lane = threadIdx.x & 31;
    int warp = threadIdx.x >> 5;
    int c    = lane;

    float cv = sw[480 * CD + c];
    float dv = sw[481 * CD + c];
    float Un = g_U[n * CD + c];
    float Vn = g_V[n * CD + c];

    float acc_i = 0.f, acc_j = 0.f;
#pragma unroll 2
    for (int m = warp; m < NN; m += 8) {
        float Um  = g_U[m * CD + c];
        float Vm  = g_V[m * CD + c];
        float enm = e[n * NN + m];
        float emn = e[m * NN + n];
        float anm = a[n * NN + m];
        float amn = a[m * NN + n];
        float atI = g_attI[n * NN + m];
        float atJ = g_attJ[m * NN + n];

        float srow = fmaxf(fmaf(enm, cv, fmaf(emn, dv, Un + Vm)), 0.f) * anm;
        float scol = fmaxf(fmaf(emn, cv, fmaf(enm, dv, Um + Vn)), 0.f) * amn;
        acc_i = fmaf(atI, srow, acc_i);
        acc_j = fmaf(atJ, scol, acc_j);
    }

    __shared__ float si[8][CD], sj[8][CD];
    si[warp][c] = acc_i;
    sj[warp][c] = acc_j;
    __syncthreads();
    if (threadIdx.x < CD) {
        float ti = 0.f, tj = 0.f;
#pragma unroll
        for (int w = 0; w < 8; w++) { ti += si[w][threadIdx.x]; tj += sj[w][threadIdx.x]; }
        g_aggi[n * CD + threadIdx.x] = ti;
        g_aggj[n * CD + threadIdx.x] = tj;
    }
}

// ---------------- node model: x_out = [x, agg_i, agg_j] @ nw + nb --------------
// TIN=4 nodes per block, grid=100. Shared staged TRANSPOSED [k][4] so the inner
// loop is one broadcast LDS.128 + 4 FMA per k; k-loop unrolled 8 to batch LDGs.
#define TIN 4
template <int LAYER>
__global__ void __launch_bounds__(FD)
node_kernel(const float* __restrict__ x_in,
            const float* __restrict__ nw,
            const float* __restrict__ nb)
{
    __shared__ float4 s_in[NIN];   // [k] -> 4 node values
    const float* xp = (LAYER == 1) ? x_in : g_x1;
    float* xo       = (LAYER == 1) ? g_x1 : g_x2;
    int i0 = blockIdx.x * TIN;

    for (int idx = threadIdx.x; idx < TIN * NIN; idx += FD) {
        int k = idx >> 2, r = idx & 3;
        int node = i0 + r;
        float v;
        if (k < FD)            v = xp[node * FD + k];
        else if (k < FD + CD)  v = g_aggi[node * CD + (k - FD)];
        else                   v = g_aggj[node * CD + (k - FD - CD)];
        ((float*)&s_in[k])[r] = v;
    }
    __syncthreads();

    int o = threadIdx.x;  // 0..239
    float b = nb[o];
    float acc0 = b, acc1 = b, acc2 = b, acc3 = b;
#pragma unroll 8
    for (int k = 0; k < NIN; k++) {
        float w = nw[k * FD + o];
        float4 s = s_in[k];
        acc0 = fmaf(s.x, w, acc0);
        acc1 = fmaf(s.y, w, acc1);
        acc2 = fmaf(s.z, w, acc2);
        acc3 = fmaf(s.w, w, acc3);
    }
    xo[(i0 + 0) * FD + o] = acc0;
    xo[(i0 + 1) * FD + o] = acc1;
    xo[(i0 + 2) * FD + o] = acc2;
    xo[(i0 + 3) * FD + o] = acc3;
}

// ---------------- final dense: out = x2 @ dw + db ------------------------------
// TID=8 rows per thread, grid=(5,50)=250 blocks, block=288. xs transposed
// [f][8] -> 2 broadcast LDS.128 per f; f-loop unrolled 8.
#define TID 8
__global__ void __launch_bounds__(288)
dense_kernel(const float* __restrict__ dw,
             const float* __restrict__ db,
             float* __restrict__ out)
{
    __shared__ __align__(16) float xs[FD][TID];
    int i0 = blockIdx.y * TID;
    int o  = blockIdx.x * 288 + threadIdx.x;  // 0..1439

    for (int idx = threadIdx.x; idx < TID * FD; idx += 288) {
        int r = idx / FD, f = idx % FD;
        xs[f][r] = g_x2[(i0 + r) * FD + f];
    }
    __syncthreads();

    float b = db[o];
    float acc[TID];
#pragma unroll
    for (int r = 0; r < TID; r++) acc[r] = b;
#pragma unroll 8
    for (int f = 0; f < FD; f++) {
        float w  = dw[f * LD + o];
        float4 a0 = *(const float4*)&xs[f][0];
        float4 a1 = *(const float4*)&xs[f][4];
        acc[0] = fmaf(a0.x, w, acc[0]);
        acc[1] = fmaf(a0.y, w, acc[1]);
        acc[2] = fmaf(a0.z, w, acc[2]);
        acc[3] = fmaf(a0.w, w, acc[3]);
        acc[4] = fmaf(a1.x, w, acc[4]);
        acc[5] = fmaf(a1.y, w, acc[5]);
        acc[6] = fmaf(a1.z, w, acc[6]);
        acc[7] = fmaf(a1.w, w, acc[7]);
    }
#pragma unroll
    for (int r = 0; r < TID; r++) out[(i0 + r) * LD + o] = acc[r];
}

// ---------------- launch --------------------------------------------------------
extern "C" void kernel_launch(void* const* d_in, const int* in_sizes, int n_in,
                              void* d_out, int out_size)
{
    const float* x  = (const float*)d_in[0];
    const float* a  = (const float*)d_in[1];
    const float* e  = (const float*)d_in[2];
    const float* c1_sw  = (const float*)d_in[3];
    const float* c1_sb  = (const float*)d_in[4];
    const float* c1_aiw = (const float*)d_in[5];
    const float* c1_aib = (const float*)d_in[6];
    const float* c1_ajw = (const float*)d_in[7];
    const float* c1_ajb = (const float*)d_in[8];
    const float* c1_nw  = (const float*)d_in[9];
    const float* c1_nb  = (const float*)d_in[10];
    const float* c1_ew  = (const float*)d_in[11];
    const float* c1_eb  = (const float*)d_in[12];
    const float* c2_sw  = (const float*)d_in[13];
    const float* c2_sb  = (const float*)d_in[14];
    const float* c2_aiw = (const float*)d_in[15];
    const float* c2_aib = (const float*)d_in[16];
    const float* c2_ajw = (const float*)d_in[17];
    const float* c2_ajb = (const float*)d_in[18];
    const float* c2_nw  = (const float*)d_in[19];
    const float* c2_nb  = (const float*)d_in[20];
    const float* c2_ew  = (const float*)d_in[21];
    const float* c2_eb  = (const float*)d_in[22];
    const float* dw = (const float*)d_in[23];
    const float* db = (const float*)d_in[24];
    float* out = (float*)d_out;

    // ---- layer 1 ----
    proj_kernel<false><<<NN, 256>>>(x, c1_sw, c1_sb);
    att_kernel<true, false><<<NN, 416>>>(a, e, c1_sw,
                                         c1_aiw, c1_aib, c1_ajw, c1_ajb,
                                         c1_ew, c1_eb);
    agg_kernel<false><<<NN, 256>>>(a, e, c1_sw);
    node_kernel<1><<<NN / TIN, FD>>>(x, c1_nw, c1_nb);

    // ---- layer 2 (layer-2 e_out is dead: final output uses x only) ----
    proj_kernel<true><<<NN, 256>>>(x, c2_sw, c2_sb);
    att_kernel<false, true><<<NN, 416>>>(a, e, c2_sw,
                                         c2_aiw, c2_aib, c2_ajw, c2_ajb,
                                         c2_ew, c2_eb);
    agg_kernel<true><<<NN, 256>>>(a, e, c2_sw);
    node_kernel<2><<<NN / TIN, FD>>>(x, c2_nw, c2_nb);

    // ---- final dense ----
    dense_kernel<<<dim3(LD / 288, NN / TID), 288>>>(dw, db, out);
}

// round 4
// speedup vs baseline: 1.7327x; 1.0648x over previous
#include <cuda_runtime.h>

#define NN 400      // nodes
#define FD 240      // node feature dim
#define CD 32       // stack channels
#define LD 1440     // labels
#define NIN 304     // F + 2C

// ---------------- scratch ----------------
__device__ float g_U[NN * CD];
__device__ float g_V[NN * CD];
__device__ float g_attI[NN * NN];
__device__ float g_attJ[NN * NN];
__device__ float g_aggi[NN * CD];
__device__ float g_aggj[NN * CD];
__device__ float g_e1[NN * NN];
__device__ float g_p1[3 * NN * FD];   // layer-1 x_out k-split partials
__device__ float g_p2[3 * NN * FD];   // layer-2 x_out k-split partials
__device__ float g_pd[2 * NN * LD];   // dense k-split partials

// ---------------- proj: U/V = x @ sw(+sb). LAYER2 reads x1 = sum of partials ----
template <bool LAYER2>
__global__ void __launch_bounds__(256)
proj_kernel(const float* __restrict__ x_in,
            const float* __restrict__ sw,
            const float* __restrict__ sb)
{
    __shared__ float xs[FD];
    __shared__ float red[4][64];
    int i = blockIdx.x;
    for (int f = threadIdx.x; f < FD; f += 256) {
        if (LAYER2) {
            xs[f] = g_p1[i * FD + f] + g_p1[NN * FD + i * FD + f]
                  + g_p1[2 * NN * FD + i * FD + f];
        } else {
            xs[f] = x_in[i * FD + f];
        }
    }
    __syncthreads();

    int ks  = threadIdx.x >> 6;
    int c64 = threadIdx.x & 63;
    int c   = c64 & 31;
    const float* w = sw + ((c64 < 32) ? 0 : FD * CD) + c;
    float acc = 0.f;
    int f0 = ks * 60;
#pragma unroll 15
    for (int f = f0; f < f0 + 60; f++) acc = fmaf(xs[f], w[f * CD], acc);
    red[ks][c64] = acc;
    __syncthreads();
    if (threadIdx.x < 64) {
        int t = threadIdx.x;
        float s = red[0][t] + red[1][t] + red[2][t] + red[3][t];
        if (t < 32) g_U[i * CD + t] = s + sb[t];
        else        g_V[i * CD + c] = s;
    }
}

// ---------------- att: per-pair gates (thread-per-pair, serial 32-dot) ----------
template <bool WRITE_E, bool USE_E1>
__global__ void __launch_bounds__(416)
att_kernel(const float* __restrict__ a, const float* __restrict__ e_in,
           const float* __restrict__ sw,
           const float* __restrict__ aiw, const float* __restrict__ aib,
           const float* __restrict__ ajw, const float* __restrict__ ajb,
           const float* __restrict__ ew,  const float* __restrict__ eb)
{
    const float* e = USE_E1 ? g_e1 : e_in;
    __shared__ float4 su[8], scv[8], sdv[8], swi[8], swj[8], swe[8];
    int p = blockIdx.x;
    if (threadIdx.x < 8) {
        int t = threadIdx.x;
        su[t]  = ((const float4*)(g_U + p * CD))[t];
        scv[t] = ((const float4*)(sw + 480 * CD))[t];
        sdv[t] = ((const float4*)(sw + 481 * CD))[t];
        swi[t] = ((const float4*)aiw)[t];
        swj[t] = ((const float4*)ajw)[t];
        swe[t] = WRITE_E ? ((const float4*)ew)[t] : make_float4(0.f, 0.f, 0.f, 0.f);
    }
    __syncthreads();
    int q = threadIdx.x;
    if (q >= NN) return;

    float epq = e[p * NN + q];
    float eqp = e[q * NN + p];
    float apq = a[p * NN + q];
    const float4* vq = (const float4*)(g_V + q * CD);
    float d1 = 0.f, d2 = 0.f, d3 = 0.f;
#pragma unroll
    for (int cc = 0; cc < 8; cc++) {
        float4 v  = vq[cc];
        float4 u  = su[cc],  c4 = scv[cc], dd = sdv[cc];
        float4 wi = swi[cc], wj = swj[cc], we = swe[cc];
        float s;
        s = fmaxf(fmaf(epq, c4.x, fmaf(eqp, dd.x, u.x + v.x)), 0.f) * apq;
        d1 = fmaf(s, wi.x, d1); d2 = fmaf(s, wj.x, d2); if (WRITE_E) d3 = fmaf(s, we.x, d3);
        s = fmaxf(fmaf(epq, c4.y, fmaf(eqp, dd.y, u.y + v.y)), 0.f) * apq;
        d1 = fmaf(s, wi.y, d1); d2 = fmaf(s, wj.y, d2); if (WRITE_E) d3 = fmaf(s, we.y, d3);
        s = fmaxf(fmaf(epq, c4.z, fmaf(eqp, dd.z, u.z + v.z)), 0.f) * apq;
        d1 = fmaf(s, wi.z, d1); d2 = fmaf(s, wj.z, d2); if (WRITE_E) d3 = fmaf(s, we.z, d3);
        s = fmaxf(fmaf(epq, c4.w, fmaf(eqp, dd.w, u.w + v.w)), 0.f) * apq;
        d1 = fmaf(s, wi.w, d1); d2 = fmaf(s, wj.w, d2); if (WRITE_E) d3 = fmaf(s, we.w, d3);
    }
    g_attI[p * NN + q] = 1.f / (1.f + __expf(-(d1 + aib[0])));
    g_attJ[p * NN + q] = 1.f / (1.f + __expf(-(d2 + ajb[0])));
    if (WRITE_E) g_e1[p * NN + q] = d3 + eb[0];
}

// ---------------- agg: recompute stack, scale by gates --------------------------
template <bool USE_E1>
__global__ void __launch_bounds__(256)
agg_kernel(const float* __restrict__ a, const float* __restrict__ e_in,
           const float* __restrict__ sw)
{
    const float* e = USE_E1 ? g_e1 : e_in;
    int n    = blockIdx.x;
    int lane = threadIdx.x & 31;
    int warp = threadIdx.x >> 5;
    int c    = lane;

    float cv = sw[480 * CD + c];
    float dv = sw[481 * CD + c];
    float Un = g_U[n * CD + c];
    float Vn = g_V[n * CD + c];

    float acc_i = 0.f, acc_j = 0.f;
#pragma unroll 2
    for (int m = warp; m < NN; m += 8) {
        float Um  = g_U[m * CD + c];
        float Vm  = g_V[m * CD + c];
        float enm = e[n * NN + m];
        float emn = e[m * NN + n];
        float anm = a[n * NN + m];
        float amn = a[m * NN + n];
        float atI = g_attI[n * NN + m];
        float atJ = g_attJ[m * NN + n];

        float srow = fmaxf(fmaf(enm, cv, fmaf(emn, dv, Un + Vm)), 0.f) * anm;
        float scol = fmaxf(fmaf(emn, cv, fmaf(enm, dv, Um + Vn)), 0.f) * amn;
        acc_i = fmaf(atI, srow, acc_i);
        acc_j = fmaf(atJ, scol, acc_j);
    }

    __shared__ float si[8][CD], sj[8][CD];
    si[warp][c] = acc_i;
    sj[warp][c] = acc_j;
    __syncthreads();
    if (threadIdx.x < CD) {
        float ti = 0.f, tj = 0.f;
#pragma unroll
        for (int w = 0; w < 8; w++) { ti += si[w][threadIdx.x]; tj += sj[w][threadIdx.x]; }
        g_aggi[n * CD + threadIdx.x] = ti;
        g_aggj[n * CD + threadIdx.x] = tj;
    }
}

// ---------------- node model partials: k-split x3, no reduce kernel -------------
// grid (100, 3), block 240. Slice z covers k in [k0, k0+len): 104/104/96.
// Partials summed in consumers (proj<2>, node_part<2> staging, dense staging).
#define TIN 4
template <int LAYER>
__global__ void __launch_bounds__(FD)
node_part(const float* __restrict__ x_in,
          const float* __restrict__ nw,
          const float* __restrict__ nb)
{
    __shared__ float4 s4[104];
    int z   = blockIdx.y;
    int k0  = z * 104;
    int len = (z == 2) ? 96 : 104;
    int i0  = blockIdx.x * TIN;
    float* po = (LAYER == 1 ? g_p1 : g_p2) + z * NN * FD;

    for (int idx = threadIdx.x; idx < len * TIN; idx += FD) {
        int k = idx >> 2, r = idx & 3;
        int gk = k0 + k;
        int node = i0 + r;
        float v;
        if (gk < FD) {
            if (LAYER == 1) v = x_in[node * FD + gk];
            else            v = g_p1[node * FD + gk] + g_p1[NN * FD + node * FD + gk]
                              + g_p1[2 * NN * FD + node * FD + gk];
        } else if (gk < FD + CD) {
            v = g_aggi[node * CD + (gk - FD)];
        } else {
            v = g_aggj[node * CD + (gk - FD - CD)];
        }
        ((float*)&s4[k])[r] = v;
    }
    __syncthreads();

    int o = threadIdx.x;
    float b = (z == 0) ? nb[o] : 0.f;
    float acc0 = b, acc1 = b, acc2 = b, acc3 = b;
    const float* wp = nw + k0 * FD + o;
#pragma unroll 8
    for (int kk = 0; kk < len; kk++) {
        float w  = wp[kk * FD];
        float4 s = s4[kk];
        acc0 = fmaf(s.x, w, acc0);
        acc1 = fmaf(s.y, w, acc1);
        acc2 = fmaf(s.z, w, acc2);
        acc3 = fmaf(s.w, w, acc3);
    }
    po[(i0 + 0) * FD + o] = acc0;
    po[(i0 + 1) * FD + o] = acc1;
    po[(i0 + 2) * FD + o] = acc2;
    po[(i0 + 3) * FD + o] = acc3;
}

// ---------------- dense partials: 16 rows/thread, k-split x2 --------------------
// grid (5, 25, 2), block 288. Slice z covers f in [z*120, z*120+120).
#define TID 16
__global__ void __launch_bounds__(288)
dense_part(const float* __restrict__ dw,
           const float* __restrict__ db)
{
    __shared__ __align__(16) float xs[120][20];   // [f][row], pad 20 for STS
    int z  = blockIdx.z;
    int f0 = z * 120;
    int i0 = blockIdx.y * TID;
    int o  = blockIdx.x * 288 + threadIdx.x;
    float* po = g_pd + z * NN * LD;

    for (int idx = threadIdx.x; idx < 120 * TID; idx += 288) {
        int r = idx / 120, f = idx % 120;
        int off = (i0 + r) * FD + f0 + f;
        xs[f][r] = g_p2[off] + g_p2[NN * FD + off] + g_p2[2 * NN * FD + off];
    }
    __syncthreads();

    float b = (z == 0) ? db[o] : 0.f;
    float acc[TID];
#pragma unroll
    for (int r = 0; r < TID; r++) acc[r] = b;
    const float* wp = dw + f0 * LD + o;
#pragma unroll 4
    for (int f = 0; f < 120; f++) {
        float w   = wp[f * LD];
        float4 a0 = *(const float4*)&xs[f][0];
        float4 a1 = *(const float4*)&xs[f][4];
        float4 a2 = *(const float4*)&xs[f][8];
        float4 a3 = *(const float4*)&xs[f][12];
        acc[0]  = fmaf(a0.x, w, acc[0]);   acc[1]  = fmaf(a0.y, w, acc[1]);
        acc[2]  = fmaf(a0.z, w, acc[2]);   acc[3]  = fmaf(a0.w, w, acc[3]);
        acc[4]  = fmaf(a1.x, w, acc[4]);   acc[5]  = fmaf(a1.y, w, acc[5]);
        acc[6]  = fmaf(a1.z, w, acc[6]);   acc[7]  = fmaf(a1.w, w, acc[7]);
        acc[8]  = fmaf(a2.x, w, acc[8]);   acc[9]  = fmaf(a2.y, w, acc[9]);
        acc[10] = fmaf(a2.z, w, acc[10]);  acc[11] = fmaf(a2.w, w, acc[11]);
        acc[12] = fmaf(a3.x, w, acc[12]);  acc[13] = fmaf(a3.y, w, acc[13]);
        acc[14] = fmaf(a3.z, w, acc[14]);  acc[15] = fmaf(a3.w, w, acc[15]);
    }
#pragma unroll
    for (int r = 0; r < TID; r++) po[(i0 + r) * LD + o] = acc[r];
}

// ---------------- dense reduce: out = pd0 + pd1 (bias folded in pd0) ------------
__global__ void __launch_bounds__(256)
dense_reduce(float* __restrict__ out)
{
    int i = blockIdx.x * 256 + threadIdx.x;
    const int N4 = NN * LD / 4;
    if (i >= N4) return;
    float4 a = ((const float4*)g_pd)[i];
    float4 b = ((const float4*)(g_pd + NN * LD))[i];
    ((float4*)out)[i] = make_float4(a.x + b.x, a.y + b.y, a.z + b.z, a.w + b.w);
}

// ---------------- launch --------------------------------------------------------
extern "C" void kernel_launch(void* const* d_in, const int* in_sizes, int n_in,
                              void* d_out, int out_size)
{
    const float* x  = (const float*)d_in[0];
    const float* a  = (const float*)d_in[1];
    const float* e  = (const float*)d_in[2];
    const float* c1_sw  = (const float*)d_in[3];
    const float* c1_sb  = (const float*)d_in[4];
    const float* c1_aiw = (const float*)d_in[5];
    const float* c1_aib = (const float*)d_in[6];
    const float* c1_ajw = (const float*)d_in[7];
    const float* c1_ajb = (const float*)d_in[8];
    const float* c1_nw  = (const float*)d_in[9];
    const float* c1_nb  = (const float*)d_in[10];
    const float* c1_ew  = (const float*)d_in[11];
    const float* c1_eb  = (const float*)d_in[12];
    const float* c2_sw  = (const float*)d_in[13];
    const float* c2_sb  = (const float*)d_in[14];
    const float* c2_aiw = (const float*)d_in[15];
    const float* c2_aib = (const float*)d_in[16];
    const float* c2_ajw = (const float*)d_in[17];
    const float* c2_ajb = (const float*)d_in[18];
    const float* c2_nw  = (const float*)d_in[19];
    const float* c2_nb  = (const float*)d_in[20];
    const float* c2_ew  = (const float*)d_in[21];
    const float* c2_eb  = (const float*)d_in[22];
    const float* dw = (const float*)d_in[23];
    const float* db = (const float*)d_in[24];
    float* out = (float*)d_out;

    // ---- layer 1 ----
    proj_kernel<false><<<NN, 256>>>(x, c1_sw, c1_sb);
    att_kernel<true, false><<<NN, 416>>>(a, e, c1_sw,
                                         c1_aiw, c1_aib, c1_ajw, c1_ajb,
                                         c1_ew, c1_eb);
    agg_kernel<false><<<NN, 256>>>(a, e, c1_sw);
    node_part<1><<<dim3(NN / TIN, 3), FD>>>(x, c1_nw, c1_nb);

    // ---- layer 2 (layer-2 e_out is dead) ----
    proj_kernel<true><<<NN, 256>>>(x, c2_sw, c2_sb);
    att_kernel<false, true><<<NN, 416>>>(a, e, c2_sw,
                                         c2_aiw, c2_aib, c2_ajw, c2_ajb,
                                         c2_ew, c2_eb);
    agg_kernel<true><<<NN, 256>>>(a, e, c2_sw);
    node_part<2><<<dim3(NN / TIN, 3), FD>>>(x, c2_nw, c2_nb);

    // ---- final dense ----
    dense_part<<<dim3(LD / 288, NN / TID, 2), 288>>>(dw, db);
    dense_reduce<<<(NN * LD / 4 + 255) / 256, 256>>>(out);
}

// round 5
// speedup vs baseline: 1.8590x; 1.0729x over previous
#include <cuda_runtime.h>

#define NN 400      // nodes
#define FD 240      // node feature dim
#define CD 32       // stack channels
#define LD 1440     // labels
#define NIN 304     // F + 2C
#define NKS 8       // node k-split count (304 = 8*38)
#define NKL 38      // node k-slice length
#define DKS 4       // dense k-split count (240 = 4*60)

// ---------------- scratch ----------------
__device__ float g_U[NN * CD];
__device__ float g_V[NN * CD];
__device__ float g_attI[NN * NN];
__device__ float g_attJ[NN * NN];
__device__ float g_aggi[NN * CD];
__device__ float g_aggj[NN * CD];
__device__ float g_e1[NN * NN];
__device__ float g_p1[NKS * NN * FD];   // layer-1 x_out k-split partials
__device__ float g_p2[NKS * NN * FD];   // layer-2 x_out k-split partials
__device__ float g_pd[DKS * NN * LD];   // dense k-split partials

__device__ __forceinline__ float sum_parts(const float* base, int off)
{
    float s = 0.f;
#pragma unroll
    for (int z = 0; z < NKS; z++) s += base[z * NN * FD + off];
    return s;
}

// ---------------- proj: U/V = x @ sw(+sb). LAYER2 reads x1 = sum of partials ----
template <bool LAYER2>
__global__ void __launch_bounds__(256)
proj_kernel(const float* __restrict__ x_in,
            const float* __restrict__ sw,
            const float* __restrict__ sb)
{
    __shared__ float xs[FD];
    __shared__ float red[4][64];
    int i = blockIdx.x;
    for (int f = threadIdx.x; f < FD; f += 256)
        xs[f] = LAYER2 ? sum_parts(g_p1, i * FD + f) : x_in[i * FD + f];
    __syncthreads();

    int ks  = threadIdx.x >> 6;
    int c64 = threadIdx.x & 63;
    int c   = c64 & 31;
    const float* w = sw + ((c64 < 32) ? 0 : FD * CD) + c;
    float acc = 0.f;
    int f0 = ks * 60;
#pragma unroll 15
    for (int f = f0; f < f0 + 60; f++) acc = fmaf(xs[f], w[f * CD], acc);
    red[ks][c64] = acc;
    __syncthreads();
    if (threadIdx.x < 64) {
        int t = threadIdx.x;
        float s = red[0][t] + red[1][t] + red[2][t] + red[3][t];
        if (t < 32) g_U[i * CD + t] = s + sb[t];
        else        g_V[i * CD + c] = s;
    }
}

// ---------------- att: per-pair gates (thread-per-pair, serial 32-dot) ----------
template <bool WRITE_E, bool USE_E1>
__global__ void __launch_bounds__(416)
att_kernel(const float* __restrict__ a, const float* __restrict__ e_in,
           const float* __restrict__ sw,
           const float* __restrict__ aiw, const float* __restrict__ aib,
           const float* __restrict__ ajw, const float* __restrict__ ajb,
           const float* __restrict__ ew,  const float* __restrict__ eb)
{
    const float* e = USE_E1 ? g_e1 : e_in;
    __shared__ float4 su[8], scv[8], sdv[8], swi[8], swj[8], swe[8];
    int p = blockIdx.x;
    if (threadIdx.x < 8) {
        int t = threadIdx.x;
        su[t]  = ((const float4*)(g_U + p * CD))[t];
        scv[t] = ((const float4*)(sw + 480 * CD))[t];
        sdv[t] = ((const float4*)(sw + 481 * CD))[t];
        swi[t] = ((const float4*)aiw)[t];
        swj[t] = ((const float4*)ajw)[t];
        swe[t] = WRITE_E ? ((const float4*)ew)[t] : make_float4(0.f, 0.f, 0.f, 0.f);
    }
    __syncthreads();
    int q = threadIdx.x;
    if (q >= NN) return;

    float epq = e[p * NN + q];
    float eqp = e[q * NN + p];
    float apq = a[p * NN + q];
    const float4* vq = (const float4*)(g_V + q * CD);
    float d1 = 0.f, d2 = 0.f, d3 = 0.f;
#pragma unroll
    for (int cc = 0; cc < 8; cc++) {
        float4 v  = vq[cc];
        float4 u  = su[cc],  c4 = scv[cc], dd = sdv[cc];
        float4 wi = swi[cc], wj = swj[cc], we = swe[cc];
        float s;
        s = fmaxf(fmaf(epq, c4.x, fmaf(eqp, dd.x, u.x + v.x)), 0.f) * apq;
        d1 = fmaf(s, wi.x, d1); d2 = fmaf(s, wj.x, d2); if (WRITE_E) d3 = fmaf(s, we.x, d3);
        s = fmaxf(fmaf(epq, c4.y, fmaf(eqp, dd.y, u.y + v.y)), 0.f) * apq;
        d1 = fmaf(s, wi.y, d1); d2 = fmaf(s, wj.y, d2); if (WRITE_E) d3 = fmaf(s, we.y, d3);
        s = fmaxf(fmaf(epq, c4.z, fmaf(eqp, dd.z, u.z + v.z)), 0.f) * apq;
        d1 = fmaf(s, wi.z, d1); d2 = fmaf(s, wj.z, d2); if (WRITE_E) d3 = fmaf(s, we.z, d3);
        s = fmaxf(fmaf(epq, c4.w, fmaf(eqp, dd.w, u.w + v.w)), 0.f) * apq;
        d1 = fmaf(s, wi.w, d1); d2 = fmaf(s, wj.w, d2); if (WRITE_E) d3 = fmaf(s, we.w, d3);
    }
    g_attI[p * NN + q] = 1.f / (1.f + __expf(-(d1 + aib[0])));
    g_attJ[p * NN + q] = 1.f / (1.f + __expf(-(d2 + ajb[0])));
    if (WRITE_E) g_e1[p * NN + q] = d3 + eb[0];
}

// ---------------- agg: recompute stack, scale by gates --------------------------
template <bool USE_E1>
__global__ void __launch_bounds__(256)
agg_kernel(const float* __restrict__ a, const float* __restrict__ e_in,
           const float* __restrict__ sw)
{
    const float* e = USE_E1 ? g_e1 : e_in;
    int n    = blockIdx.x;
    int lane = threadIdx.x & 31;
    int warp = threadIdx.x >> 5;
    int c    = lane;

    float cv = sw[480 * CD + c];
    float dv = sw[481 * CD + c];
    float Un = g_U[n * CD + c];
    float Vn = g_V[n * CD + c];

    float acc_i = 0.f, acc_j = 0.f;
#pragma unroll 2
    for (int m = warp; m < NN; m += 8) {
        float Um  = g_U[m * CD + c];
        float Vm  = g_V[m * CD + c];
        float enm = e[n * NN + m];
        float emn = e[m * NN + n];
        float anm = a[n * NN + m];
        float amn = a[m * NN + n];
        float atI = g_attI[n * NN + m];
        float atJ = g_attJ[m * NN + n];

        float srow = fmaxf(fmaf(enm, cv, fmaf(emn, dv, Un + Vm)), 0.f) * anm;
        float scol = fmaxf(fmaf(emn, cv, fmaf(enm, dv, Um + Vn)), 0.f) * amn;
        acc_i = fmaf(atI, srow, acc_i);
        acc_j = fmaf(atJ, scol, acc_j);
    }

    __shared__ float si[8][CD], sj[8][CD];
    si[warp][c] = acc_i;
    sj[warp][c] = acc_j;
    __syncthreads();
    if (threadIdx.x < CD) {
        float ti = 0.f, tj = 0.f;
#pragma unroll
        for (int w = 0; w < 8; w++) { ti += si[w][threadIdx.x]; tj += sj[w][threadIdx.x]; }
        g_aggi[n * CD + threadIdx.x] = ti;
        g_aggj[n * CD + threadIdx.x] = tj;
    }
}

// ---------------- node model partials: k-split x8, compile-time slice = 38 ------
// grid (100, 8), block 240 -> 192k threads (~40 warps/SM). Fully unrollable
// 38-iteration loop lets ptxas front-batch the weight LDGs.
#define TIN 4
template <int LAYER>
__global__ void __launch_bounds__(FD)
node_part(const float* __restrict__ x_in,
          const float* __restrict__ nw,
          const float* __restrict__ nb)
{
    __shared__ float4 s4[NKL];
    int z   = blockIdx.y;
    int k0  = z * NKL;
    int i0  = blockIdx.x * TIN;
    float* po = (LAYER == 1 ? g_p1 : g_p2) + z * NN * FD;

    for (int idx = threadIdx.x; idx < NKL * TIN; idx += FD) {
        int k = idx >> 2, r = idx & 3;
        int gk = k0 + k;
        int node = i0 + r;
        float v;
        if (gk < FD) {
            if (LAYER == 1) v = x_in[node * FD + gk];
            else            v = sum_parts(g_p1, node * FD + gk);
        } else if (gk < FD + CD) {
            v = g_aggi[node * CD + (gk - FD)];
        } else {
            v = g_aggj[node * CD + (gk - FD - CD)];
        }
        ((float*)&s4[k])[r] = v;
    }
    __syncthreads();

    int o = threadIdx.x;
    float b = (z == 0) ? nb[o] : 0.f;
    float acc0 = b, acc1 = b, acc2 = b, acc3 = b;
    const float* wp = nw + k0 * FD + o;
#pragma unroll
    for (int kk = 0; kk < NKL; kk++) {
        float w  = wp[kk * FD];
        float4 s = s4[kk];
        acc0 = fmaf(s.x, w, acc0);
        acc1 = fmaf(s.y, w, acc1);
        acc2 = fmaf(s.z, w, acc2);
        acc3 = fmaf(s.w, w, acc3);
    }
    po[(i0 + 0) * FD + o] = acc0;
    po[(i0 + 1) * FD + o] = acc1;
    po[(i0 + 2) * FD + o] = acc2;
    po[(i0 + 3) * FD + o] = acc3;
}

// ---------------- dense partials: 16 rows/thread, k-split x4 (60 f each) --------
// grid (5, 25, 4) = 500 blocks, block 288 -> ~30 warps/SM.
#define TID 16
__global__ void __launch_bounds__(288)
dense_part(const float* __restrict__ dw,
           const float* __restrict__ db)
{
    __shared__ __align__(16) float xs[60][20];   // [f][row], pad 20
    int z  = blockIdx.z;
    int f0 = z * 60;
    int i0 = blockIdx.y * TID;
    int o  = blockIdx.x * 288 + threadIdx.x;
    float* po = g_pd + z * NN * LD;

    for (int idx = threadIdx.x; idx < 60 * TID; idx += 288) {
        int r = idx / 60, f = idx % 60;
        xs[f][r] = sum_parts(g_p2, (i0 + r) * FD + f0 + f);
    }
    __syncthreads();

    float b = (z == 0) ? db[o] : 0.f;
    float acc[TID];
#pragma unroll
    for (int r = 0; r < TID; r++) acc[r] = b;
    const float* wp = dw + f0 * LD + o;
#pragma unroll 5
    for (int f = 0; f < 60; f++) {
        float w   = wp[f * LD];
        float4 a0 = *(const float4*)&xs[f][0];
        float4 a1 = *(const float4*)&xs[f][4];
        float4 a2 = *(const float4*)&xs[f][8];
        float4 a3 = *(const float4*)&xs[f][12];
        acc[0]  = fmaf(a0.x, w, acc[0]);   acc[1]  = fmaf(a0.y, w, acc[1]);
        acc[2]  = fmaf(a0.z, w, acc[2]);   acc[3]  = fmaf(a0.w, w, acc[3]);
        acc[4]  = fmaf(a1.x, w, acc[4]);   acc[5]  = fmaf(a1.y, w, acc[5]);
        acc[6]  = fmaf(a1.z, w, acc[6]);   acc[7]  = fmaf(a1.w, w, acc[7]);
        acc[8]  = fmaf(a2.x, w, acc[8]);   acc[9]  = fmaf(a2.y, w, acc[9]);
        acc[10] = fmaf(a2.z, w, acc[10]);  acc[11] = fmaf(a2.w, w, acc[11]);
        acc[12] = fmaf(a3.x, w, acc[12]);  acc[13] = fmaf(a3.y, w, acc[13]);
        acc[14] = fmaf(a3.z, w, acc[14]);  acc[15] = fmaf(a3.w, w, acc[15]);
    }
#pragma unroll
    for (int r = 0; r < TID; r++) po[(i0 + r) * LD + o] = acc[r];
}

// ---------------- dense reduce: out = sum of 4 partials (bias in partial 0) -----
__global__ void __launch_bounds__(256)
dense_reduce(float* __restrict__ out)
{
    int i = blockIdx.x * 256 + threadIdx.x;
    const int N4 = NN * LD / 4;
    if (i >= N4) return;
    float4 s = ((const float4*)g_pd)[i];
#pragma unroll
    for (int z = 1; z < DKS; z++) {
        float4 p = ((const float4*)(g_pd + z * NN * LD))[i];
        s.x += p.x; s.y += p.y; s.z += p.z; s.w += p.w;
    }
    ((float4*)out)[i] = s;
}

// ---------------- launch --------------------------------------------------------
extern "C" void kernel_launch(void* const* d_in, const int* in_sizes, int n_in,
                              void* d_out, int out_size)
{
    const float* x  = (const float*)d_in[0];
    const float* a  = (const float*)d_in[1];
    const float* e  = (const float*)d_in[2];
    const float* c1_sw  = (const float*)d_in[3];
    const float* c1_sb  = (const float*)d_in[4];
    const float* c1_aiw = (const float*)d_in[5];
    const float* c1_aib = (const float*)d_in[6];
    const float* c1_ajw = (const float*)d_in[7];
    const float* c1_ajb = (const float*)d_in[8];
    const float* c1_nw  = (const float*)d_in[9];
    const float* c1_nb  = (const float*)d_in[10];
    const float* c1_ew  = (const float*)d_in[11];
    const float* c1_eb  = (const float*)d_in[12];
    const float* c2_sw  = (const float*)d_in[13];
    const float* c2_sb  = (const float*)d_in[14];
    const float* c2_aiw = (const float*)d_in[15];
    const float* c2_aib = (const float*)d_in[16];
    const float* c2_ajw = (const float*)d_in[17];
    const float* c2_ajb = (const float*)d_in[18];
    const float* c2_nw  = (const float*)d_in[19];
    const float* c2_nb  = (const float*)d_in[20];
    const float* c2_ew  = (const float*)d_in[21];
    const float* c2_eb  = (const float*)d_in[22];
    const float* dw = (const float*)d_in[23];
    const float* db = (const float*)d_in[24];
    float* out = (float*)d_out;

    // ---- layer 1 ----
    proj_kernel<false><<<NN, 256>>>(x, c1_sw, c1_sb);
    att_kernel<true, false><<<NN, 416>>>(a, e, c1_sw,
                                         c1_aiw, c1_aib, c1_ajw, c1_ajb,
                                         c1_ew, c1_eb);
    agg_kernel<false><<<NN, 256>>>(a, e, c1_sw);
    node_part<1><<<dim3(NN / TIN, NKS), FD>>>(x, c1_nw, c1_nb);

    // ---- layer 2 (layer-2 e_out is dead) ----
    proj_kernel<true><<<NN, 256>>>(x, c2_sw, c2_sb);
    att_kernel<false, true><<<NN, 416>>>(a, e, c2_sw,
                                         c2_aiw, c2_aib, c2_ajw, c2_ajb,
                                         c2_ew, c2_eb);
    agg_kernel<true><<<NN, 256>>>(a, e, c2_sw);
    node_part<2><<<dim3(NN / TIN, NKS), FD>>>(x, c2_nw, c2_nb);

    // ---- final dense ----
    dense_part<<<dim3(LD / 288, NN / TID, DKS), 288>>>(dw, db);
    dense_reduce<<<(NN * LD / 4 + 255) / 256, 256>>>(out);
}